// round 3
// baseline (speedup 1.0000x reference)
#include <cuda_runtime.h>
#include <stdint.h>

#define BB   8
#define NN   4096
#define CPN  57
#define KK   16
#define THR  0.04f
#define GC   5
#define NC   125

// ---------------- scratch (device globals; no allocation allowed) -----------
__device__ int    g_knn_idx[BB * NN * KK];
__device__ float  g_knn_dist[BB * NN * KK];
__device__ int    g_cnt[BB * 128];
__device__ int    g_off[BB * 128];
__device__ int    g_cur[BB * 128];
__device__ float4 g_sx[BB * NN];
__device__ int    g_sj[BB * NN];

// ---------------------------------------------------------------------------
// f32x2 packed helpers
// ---------------------------------------------------------------------------
typedef unsigned long long u64;
__device__ __forceinline__ u64 f2pack(float a, float b) {
    u64 r; asm("mov.b64 %0,{%1,%2};" : "=l"(r) : "f"(a), "f"(b)); return r;
}
__device__ __forceinline__ void f2unpack(u64 v, float& a, float& b) {
    asm("mov.b64 {%0,%1},%2;" : "=f"(a), "=f"(b) : "l"(v));
}
__device__ __forceinline__ u64 ffma2(u64 a, u64 b, u64 c) {
    u64 d; asm("fma.rn.f32x2 %0,%1,%2,%3;" : "=l"(d) : "l"(a), "l"(b), "l"(c));
    return d;
}
__device__ __forceinline__ void lds2x64(u64& a, u64& b, unsigned addr) {
    asm volatile("ld.shared.v2.b64 {%0,%1},[%2];"
                 : "=l"(a), "=l"(b) : "r"(addr));
}

// ---------------------------------------------------------------------------
// Grid build: cell id (cell size == radius == 0.2, 5^3 cells per batch)
// ---------------------------------------------------------------------------
__device__ __forceinline__ int cell_of(float x, float y, float z) {
    int cx = min((int)(x * 5.0f), 4);
    int cy = min((int)(y * 5.0f), 4);
    int cz = min((int)(z * 5.0f), 4);
    return (cx * 5 + cy) * 5 + cz;
}

__global__ void grid_zero() {
    int t = blockIdx.x * 256 + threadIdx.x;
    if (t < BB * 128) g_cnt[t] = 0;
}

__global__ void grid_count(const float* __restrict__ xyz) {
    int p = blockIdx.x * 256 + threadIdx.x;
    float x = xyz[p * 3 + 0], y = xyz[p * 3 + 1], z = xyz[p * 3 + 2];
    atomicAdd(&g_cnt[(p >> 12) * 128 + cell_of(x, y, z)], 1);
}

__global__ void grid_scan() {
    int b = threadIdx.x;
    if (b < BB) {
        int acc = 0;
        for (int c = 0; c < NC; c++) {
            g_off[b * 128 + c] = acc;
            g_cur[b * 128 + c] = acc;
            acc += g_cnt[b * 128 + c];
        }
        g_off[b * 128 + NC] = acc;   // sentinel
    }
}

__global__ void grid_scatter(const float* __restrict__ xyz) {
    int p = blockIdx.x * 256 + threadIdx.x;
    int b = p >> 12, i = p & (NN - 1);
    float x = xyz[p * 3 + 0], y = xyz[p * 3 + 1], z = xyz[p * 3 + 2];
    int cell = cell_of(x, y, z);
    int pos = atomicAdd(&g_cur[b * 128 + cell], 1);
    float sq = fmaf(z, z, fmaf(y, y, x * x));
    g_sx[(b << 12) + pos] = make_float4(x, y, z, sq);
    g_sj[(b << 12) + pos] = i;
}

// ---------------------------------------------------------------------------
// kNN query: one thread per SORTED point (warp lanes share cell ranges).
// ---------------------------------------------------------------------------
__global__ __launch_bounds__(256, 8) void knn_query() {
    const int b = blockIdx.y;
    const int slot = blockIdx.x * 256 + threadIdx.x;
    const float4 q = g_sx[(b << 12) + slot];
    const int qi = g_sj[(b << 12) + slot];
    const float qsq = q.w;
    const int cx = min((int)(q.x * 5.0f), 4);
    const int cy = min((int)(q.y * 5.0f), 4);
    const int cz = min((int)(q.z * 5.0f), 4);
    const float qoff = 0.5f * (qsq - THR) - 1e-5f;

    float bestd[KK];
    int   bestj[KK];
#pragma unroll
    for (int s = 0; s < KK; s++) { bestd[s] = 3.0e38f; bestj[s] = qi; }
    float maxv = 3.0e38f;
    int   maxslot = 0;
    int   maxj = qi;

    const int czlo = max(cz - 1, 0), czhi = min(cz + 1, 4);
    for (int dx = -1; dx <= 1; dx++) {
        int ncx = cx + dx; if (ncx < 0 || ncx > 4) continue;
        for (int dy = -1; dy <= 1; dy++) {
            int ncy = cy + dy; if (ncy < 0 || ncy > 4) continue;
            int cbase = b * 128 + (ncx * 5 + ncy) * 5;
            int sbeg = g_off[cbase + czlo];
            int send = g_off[cbase + czhi + 1];
#pragma unroll 2
            for (int s = sbeg; s < send; s++) {
                float4 c = g_sx[(b << 12) + s];
                float dot = fmaf(q.z, c.z, fmaf(q.y, c.y, q.x * c.x));
                float rhs = fmaf(0.5f, c.w, qoff);
                if (dot >= rhs) {
                    float t1 = qsq + c.w;
                    float d = __fsub_rn(t1, __fmul_rn(2.0f, dot));
                    if (d <= THR && d < maxv) {
                        int j = g_sj[(b << 12) + s];
#pragma unroll
                        for (int u = 0; u < KK; u++)
                            if (u == maxslot) { bestd[u] = d; bestj[u] = j; }
                        maxv = bestd[0]; maxj = bestj[0]; maxslot = 0;
#pragma unroll
                        for (int u = 1; u < KK; u++) {
                            bool g = (bestd[u] > maxv) ||
                                     (bestd[u] == maxv && bestj[u] > maxj);
                            if (g) { maxv = bestd[u]; maxj = bestj[u]; maxslot = u; }
                        }
                    }
                }
            }
        }
    }

    const int base = (b * NN + qi) * KK;
#pragma unroll
    for (int s = 0; s < KK; s++) {
        float d = fmaxf(bestd[s], 0.0f);
        int   j = bestj[s];
        if (d > THR) { j = qi; d = 0.0f; }
        g_knn_idx[base + s]  = j;
        g_knn_dist[base + s] = d;
    }
}

// ============================================================================
// feat kernel: one warp per point group (PPW=4), all weights in SMEM.
// dfg2: 16-k batched; hidT rows are read via WARP-BROADCAST LDS.128 (all
// lanes same address -> single crossbar access), weights per-lane LDS.64.
// Crossbar/row drops 2304B -> ~320B; loop is now FMA/issue-bound.
// ============================================================================
#define WARPS 16
#define PPW   4
#define TPB   (WARPS * 32)

#define O_W1   0
#define O_B1   448
#define O_W2   512
#define O_B2   4608
#define O_M1   4672
#define O_MB1  13248
#define O_M2   13376
#define O_MB2  21568
#define O_SC   21632
#define O_SCB  25280
#define O_SCR  25344
#define WSCR   1552
#define SMEM_FLOATS (O_SCR + WARPS * WSCR)
#define SMEM_BYTES  (SMEM_FLOATS * 4)

__global__ __launch_bounds__(TPB, 1)
void feat_kernel(const float* __restrict__ xyz,
                 const float* __restrict__ points,
                 const float* __restrict__ w1, const float* __restrict__ b1,
                 const float* __restrict__ w2, const float* __restrict__ b2,
                 const float* __restrict__ m1, const float* __restrict__ mb1,
                 const float* __restrict__ m2, const float* __restrict__ mb2,
                 const float* __restrict__ sc, const float* __restrict__ scb,
                 float* __restrict__ out) {
    extern __shared__ float sm[];

    for (int t = threadIdx.x; t < 448; t += TPB)  sm[O_W1 + t]  = w1[t];
    for (int t = threadIdx.x; t < 64;  t += TPB)  sm[O_B1 + t]  = b1[t];
    for (int t = threadIdx.x; t < 4096; t += TPB) sm[O_W2 + t]  = w2[t];
    for (int t = threadIdx.x; t < 64;  t += TPB)  sm[O_B2 + t]  = b2[t];
    for (int t = threadIdx.x; t < 8576; t += TPB) sm[O_M1 + t]  = m1[t];
    for (int t = threadIdx.x; t < 128; t += TPB)  sm[O_MB1 + t] = mb1[t];
    for (int t = threadIdx.x; t < 8192; t += TPB) sm[O_M2 + t]  = m2[t];
    for (int t = threadIdx.x; t < 64;  t += TPB)  sm[O_MB2 + t] = mb2[t];
    for (int t = threadIdx.x; t < 3648; t += TPB) sm[O_SC + t]  = sc[t];
    for (int t = threadIdx.x; t < 64;  t += TPB)  sm[O_SCB + t] = scb[t];
    __syncthreads();

    const int warp = threadIdx.x >> 5;
    const int lane = threadIdx.x & 31;
    const int c0 = 2 * lane, c1 = c0 + 1;
    const int c4 = 4 * lane;

    float w1r0[7], w1r1[7];
#pragma unroll
    for (int t = 0; t < 7; t++) {
        w1r0[t] = sm[O_W1 + t * 64 + c0];
        w1r1[t] = sm[O_W1 + t * 64 + c1];
    }
    const float lb10 = sm[O_B1 + c0], lb11 = sm[O_B1 + c1];
    const float lb20 = sm[O_B2 + c0], lb21 = sm[O_B2 + c1];

    float* ws    = sm + O_SCR + warp * WSCR;   // hidT / h128 / prow
    float* h67   = ws + 1280;                  // 4 x 68
    float* h128b = ws;                         // 4 x 128 (after dfg)
    float* prowb = ws + 512;                   // 4 x 60  (after dfg)

    const unsigned smbase = (unsigned)__cvta_generic_to_shared(sm);
    const unsigned hidT32 = smbase + (unsigned)(O_SCR + warp * WSCR) * 4u;

    const int pbase = blockIdx.x * (WARPS * PPW) + warp * PPW;

    // ---------------- per-point dfg phase --------------------------------
#pragma unroll 1
    for (int pp = 0; pp < PPW; pp++) {
        const int p = pbase + pp;
        const int b = p >> 12;
        const float qx = xyz[p * 3 + 0];
        const float qy = xyz[p * 3 + 1];
        const float qz = xyz[p * 3 + 2];

        int   myidx = p & (NN - 1);
        float mydist = 0.0f;
        if (lane < KK) {
            myidx  = g_knn_idx[p * KK + lane];
            mydist = g_knn_dist[p * KK + lane];
        }

        // ---- dfg layer 1: 4 k at a time, swizzled transpose store -------
        // physical slot for (row t, k-group g) is g ^ ((t>>3)&3)
        const int sA = (c0 >> 3) & 3;
#pragma unroll
        for (int kb = 0; kb < 4; kb++) {
            float2 hk[4];
#pragma unroll
            for (int kk = 0; kk < 4; kk++) {
                const int k = kb * 4 + kk;
                const int   j  = __shfl_sync(0xffffffffu, myidx, k);
                const float dk = __shfl_sync(0xffffffffu, mydist, k);
                const float* nb = xyz + ((size_t)(b << 12) + j) * 3;
                const float g0 = nb[0], g1 = nb[1], g2 = nb[2];
                const float g3 = g0 - qx, g4 = g1 - qy, g5 = g2 - qz;
                float h0 = lb10, h1 = lb11;
                h0 = fmaf(g0, w1r0[0], h0); h1 = fmaf(g0, w1r1[0], h1);
                h0 = fmaf(g1, w1r0[1], h0); h1 = fmaf(g1, w1r1[1], h1);
                h0 = fmaf(g2, w1r0[2], h0); h1 = fmaf(g2, w1r1[2], h1);
                h0 = fmaf(g3, w1r0[3], h0); h1 = fmaf(g3, w1r1[3], h1);
                h0 = fmaf(g4, w1r0[4], h0); h1 = fmaf(g4, w1r1[4], h1);
                h0 = fmaf(g5, w1r0[5], h0); h1 = fmaf(g5, w1r1[5], h1);
                h0 = fmaf(dk, w1r0[6], h0); h1 = fmaf(dk, w1r1[6], h1);
                hk[kk] = make_float2(fmaxf(h0, 0.0f), fmaxf(h1, 0.0f));
            }
            const int slot = (kb ^ sA) << 2;
            *(float4*)(ws + c0 * 20 + slot) =
                make_float4(hk[0].x, hk[1].x, hk[2].x, hk[3].x);
            *(float4*)(ws + c1 * 20 + slot) =
                make_float4(hk[0].y, hk[1].y, hk[2].y, hk[3].y);
        }
        __syncwarp();

        // ---- dfg layer 2: 16-k batched, broadcast hid reads -------------
        u64 a0[8], a1[8];
        {
            u64 bb0 = f2pack(lb20, lb20), bb1 = f2pack(lb21, lb21);
#pragma unroll
            for (int m = 0; m < 8; m++) { a0[m] = bb0; a1[m] = bb1; }
        }
#pragma unroll
        for (int o = 0; o < 8; o++) {
#pragma unroll
            for (int tt = 0; tt < 8; tt++) {
                const int t = o * 8 + tt;
                const int sw = (t >> 3) & 3;     // compile-time constant
                const float2 w = *(const float2*)&sm[O_W2 + t * 64 + c0];
                const u64 w00 = f2pack(w.x, w.x);
                const u64 w11 = f2pack(w.y, w.y);
                const unsigned rowa = hidT32 + (unsigned)(t * 20) * 4u;
#pragma unroll
                for (int g = 0; g < 4; g++) {
                    u64 h01, h23;                // broadcast: lane-invariant addr
                    lds2x64(h01, h23, rowa + (unsigned)(((g ^ sw) << 2) * 4));
                    const int m = g << 1;
                    a0[m]     = ffma2(h01, w00, a0[m]);
                    a0[m + 1] = ffma2(h23, w00, a0[m + 1]);
                    a1[m]     = ffma2(h01, w11, a1[m]);
                    a1[m + 1] = ffma2(h23, w11, a1[m + 1]);
                }
            }
        }
        __syncwarp();

        // ---- aggregation over k -----------------------------------------
        float agg0 = 0.0f, agg1 = 0.0f;
#pragma unroll
        for (int m = 0; m < 8; m++) {
            float oE0, oO0, oE1, oO1;
            f2unpack(a0[m], oE0, oO0);
            f2unpack(a1[m], oE1, oO1);
#pragma unroll
            for (int kk = 0; kk < 2; kk++) {
                const int k = 2 * m + kk;
                const float o0 = kk ? oO0 : oE0;
                const float o1 = kk ? oO1 : oE1;
                const int   j  = __shfl_sync(0xffffffffu, myidx, k);
                const float dk = __shfl_sync(0xffffffffu, mydist, k);
                const float* nb = xyz + ((size_t)(b << 12) + j) * 3;
                const float g0 = nb[0], g1 = nb[1], g2 = nb[2];
                const float* prow = points + ((size_t)(b << 12) + j) * CPN;
                float gp0 = (c0 >= 7) ? prow[c0 - 7] : 0.0f;
                float gp1 = (c1 >= 7) ? prow[c1 - 7] : 0.0f;
                if (lane == 0)      { gp0 = g0; gp1 = g1; }
                else if (lane == 1) { gp0 = g2; gp1 = g0 - qx; }
                else if (lane == 2) { gp0 = g1 - qy; gp1 = g2 - qz; }
                else if (lane == 3) { gp0 = dk; }
                agg0 = fmaf(o0, gp0, agg0);
                agg1 = fmaf(o1, gp1, agg1);
            }
        }
        agg0 *= 0.0625f; agg1 *= 0.0625f;

        float* hb = h67 + pp * 68;
        if (lane == 0) { hb[0] = qx; hb[1] = qy; hb[2] = qz; }
        hb[3 + c0] = agg0;
        hb[3 + c1] = agg1;
        __syncwarp();
    }

    // ---------------- joint MLP phase (4 points) -------------------------
    // mlp1: [67] -> [128], relu
    {
        u64 acc[PPW][2];
        const float4 bbv = *(const float4*)&sm[O_MB1 + c4];
        const u64 bb01 = f2pack(bbv.x, bbv.y), bb23 = f2pack(bbv.z, bbv.w);
#pragma unroll
        for (int pp = 0; pp < PPW; pp++) { acc[pp][0] = bb01; acc[pp][1] = bb23; }
        const unsigned m1base = smbase + (unsigned)(O_M1 + c4) * 4u;
#pragma unroll 4
        for (int t = 0; t < 67; t++) {
            u64 w01, w23; lds2x64(w01, w23, m1base + (unsigned)(t * 128) * 4u);
#pragma unroll
            for (int pp = 0; pp < PPW; pp++) {
                const float v = h67[pp * 68 + t];
                const u64 vv = f2pack(v, v);
                acc[pp][0] = ffma2(w01, vv, acc[pp][0]);
                acc[pp][1] = ffma2(w23, vv, acc[pp][1]);
            }
        }
        __syncwarp();   // dfg reads of ws fully done before overwrite
#pragma unroll
        for (int pp = 0; pp < PPW; pp++) {
            float x0, x1, x2, x3;
            f2unpack(acc[pp][0], x0, x1);
            f2unpack(acc[pp][1], x2, x3);
            *(float4*)&h128b[pp * 128 + c4] =
                make_float4(fmaxf(x0, 0.0f), fmaxf(x1, 0.0f),
                            fmaxf(x2, 0.0f), fmaxf(x3, 0.0f));
        }
    }

    // stage self point rows
#pragma unroll
    for (int pp = 0; pp < PPW; pp++) {
        const float* ps = points + (size_t)(pbase + pp) * CPN;
        for (int t = lane; t < CPN; t += 32) prowb[pp * 60 + t] = ps[t];
    }
    __syncwarp();

    // mlp2: [128] -> [64]
    u64 om[PPW];
    {
        const u64 mb = *(const u64*)&sm[O_MB2 + c0];
#pragma unroll
        for (int pp = 0; pp < PPW; pp++) om[pp] = mb;
#pragma unroll 4
        for (int t = 0; t < 128; t++) {
            const u64 wp = *(const u64*)&sm[O_M2 + t * 64 + c0];
#pragma unroll
            for (int pp = 0; pp < PPW; pp++) {
                const float v = h128b[pp * 128 + t];
                om[pp] = ffma2(wp, f2pack(v, v), om[pp]);
            }
        }
    }

    // shortcut: points @ sc_w + sc_b
    u64 orr[PPW];
    {
        const u64 sb = *(const u64*)&sm[O_SCB + c0];
#pragma unroll
        for (int pp = 0; pp < PPW; pp++) orr[pp] = sb;
#pragma unroll 4
        for (int t = 0; t < CPN; t++) {
            const u64 wp = *(const u64*)&sm[O_SC + t * 64 + c0];
#pragma unroll
            for (int pp = 0; pp < PPW; pp++) {
                const float v = prowb[pp * 60 + t];
                orr[pp] = ffma2(wp, f2pack(v, v), orr[pp]);
            }
        }
    }

#pragma unroll
    for (int pp = 0; pp < PPW; pp++) {
        float o0, o1, r0, r1;
        f2unpack(om[pp], o0, o1);
        f2unpack(orr[pp], r0, r1);
        const int p = pbase + pp;
        *(float2*)&out[(size_t)p * 64 + c0] =
            make_float2(fmaxf(r0 + o0, 0.0f), fmaxf(r1 + o1, 0.0f));
    }
}

// ============================================================================
extern "C" void kernel_launch(void* const* d_in, const int* in_sizes, int n_in,
                              void* d_out, int out_size) {
    const float* xyz    = (const float*)d_in[0];
    const float* points = (const float*)d_in[1];
    const float* w1     = (const float*)d_in[2];
    const float* b1     = (const float*)d_in[3];
    const float* w2     = (const float*)d_in[4];
    const float* b2     = (const float*)d_in[5];
    const float* m1     = (const float*)d_in[6];
    const float* mb1    = (const float*)d_in[7];
    const float* m2     = (const float*)d_in[8];
    const float* mb2    = (const float*)d_in[9];
    const float* sc     = (const float*)d_in[10];
    const float* scb    = (const float*)d_in[11];
    float* out = (float*)d_out;
    (void)in_sizes; (void)n_in; (void)out_size;

    grid_zero<<<4, 256>>>();
    grid_count<<<BB * NN / 256, 256>>>(xyz);
    grid_scan<<<1, 32>>>();
    grid_scatter<<<BB * NN / 256, 256>>>(xyz);
    knn_query<<<dim3(NN / 256, BB), 256>>>();

    cudaFuncSetAttribute(feat_kernel,
                         cudaFuncAttributeMaxDynamicSharedMemorySize,
                         SMEM_BYTES);
    feat_kernel<<<BB * NN / (WARPS * PPW), TPB, SMEM_BYTES>>>(
        xyz, points, w1, b1, w2, b2, m1, mb1, m2, mb2, sc, scb, out);
}

// round 4
// speedup vs baseline: 1.2116x; 1.2116x over previous
#include <cuda_runtime.h>
#include <stdint.h>

#define BB   8
#define NN   4096
#define CPN  57
#define KK   16
#define THR  0.04f
#define NC   125

// ---------------- scratch (device globals; no allocation allowed) -----------
__device__ int    g_knn_idx[BB * NN * KK];
__device__ float  g_knn_dist[BB * NN * KK];
__device__ int    g_off[BB * 128];
__device__ float4 g_sx[BB * NN];
__device__ int    g_sj[BB * NN];
__device__ float  g_h67[BB * NN * 68];     // [agg(64) | xyz(3) | pad]

// ---------------------------------------------------------------------------
// f32x2 packed helpers
// ---------------------------------------------------------------------------
typedef unsigned long long u64;
__device__ __forceinline__ u64 f2pack(float a, float b) {
    u64 r; asm("mov.b64 %0,{%1,%2};" : "=l"(r) : "f"(a), "f"(b)); return r;
}
__device__ __forceinline__ void f2unpack(u64 v, float& a, float& b) {
    asm("mov.b64 {%0,%1},%2;" : "=f"(a), "=f"(b) : "l"(v));
}
__device__ __forceinline__ u64 ffma2(u64 a, u64 b, u64 c) {
    u64 d; asm("fma.rn.f32x2 %0,%1,%2,%3;" : "=l"(d) : "l"(a), "l"(b), "l"(c));
    return d;
}
__device__ __forceinline__ void lds2x64(u64& a, u64& b, unsigned addr) {
    asm volatile("ld.shared.v2.b64 {%0,%1},[%2];"
                 : "=l"(a), "=l"(b) : "r"(addr));
}

// ---------------------------------------------------------------------------
// Fused grid build: one block per batch.  count -> scan -> scatter in SMEM.
// ---------------------------------------------------------------------------
__device__ __forceinline__ int cell_of(float x, float y, float z) {
    int cx = min((int)(x * 5.0f), 4);
    int cy = min((int)(y * 5.0f), 4);
    int cz = min((int)(z * 5.0f), 4);
    return (cx * 5 + cy) * 5 + cz;
}

__global__ void grid_build(const float* __restrict__ xyz) {
    __shared__ int scnt[NC];
    __shared__ int soff[NC + 1];
    __shared__ int scur[NC];
    const int b = blockIdx.x;
    const float* bx = xyz + (size_t)b * NN * 3;

    for (int t = threadIdx.x; t < NC; t += 512) scnt[t] = 0;
    __syncthreads();

    for (int i = threadIdx.x; i < NN; i += 512) {
        float x = bx[i * 3 + 0], y = bx[i * 3 + 1], z = bx[i * 3 + 2];
        atomicAdd(&scnt[cell_of(x, y, z)], 1);
    }
    __syncthreads();

    if (threadIdx.x == 0) {
        int acc = 0;
        for (int c = 0; c < NC; c++) { soff[c] = acc; scur[c] = acc; acc += scnt[c]; }
        soff[NC] = acc;
    }
    __syncthreads();

    for (int t = threadIdx.x; t <= NC; t += 512) g_off[b * 128 + t] = soff[t];

    for (int i = threadIdx.x; i < NN; i += 512) {
        float x = bx[i * 3 + 0], y = bx[i * 3 + 1], z = bx[i * 3 + 2];
        int cell = cell_of(x, y, z);
        int pos = atomicAdd(&scur[cell], 1);
        float sq = fmaf(z, z, fmaf(y, y, x * x));
        g_sx[(b << 12) + pos] = make_float4(x, y, z, sq);
        g_sj[(b << 12) + pos] = i;
    }
}

// ---------------------------------------------------------------------------
// kNN query (exact R2 config: 128-thread blocks, no unroll pragma).
// ---------------------------------------------------------------------------
__global__ void knn_query() {
    const int b = blockIdx.y;
    const int slot = blockIdx.x * 128 + threadIdx.x;
    const float4 q = g_sx[(b << 12) + slot];
    const int qi = g_sj[(b << 12) + slot];
    const float qsq = q.w;
    const int cx = min((int)(q.x * 5.0f), 4);
    const int cy = min((int)(q.y * 5.0f), 4);
    const int cz = min((int)(q.z * 5.0f), 4);
    const float qoff = 0.5f * (qsq - THR) - 1e-5f;

    float bestd[KK];
    int   bestj[KK];
#pragma unroll
    for (int s = 0; s < KK; s++) { bestd[s] = 3.0e38f; bestj[s] = qi; }
    float maxv = 3.0e38f;
    int   maxslot = 0;
    int   maxj = qi;

    const int czlo = max(cz - 1, 0), czhi = min(cz + 1, 4);
    for (int dx = -1; dx <= 1; dx++) {
        int ncx = cx + dx; if (ncx < 0 || ncx > 4) continue;
        for (int dy = -1; dy <= 1; dy++) {
            int ncy = cy + dy; if (ncy < 0 || ncy > 4) continue;
            int cbase = b * 128 + (ncx * 5 + ncy) * 5;
            int sbeg = g_off[cbase + czlo];
            int send = g_off[cbase + czhi + 1];
            for (int s = sbeg; s < send; s++) {
                float4 c = g_sx[(b << 12) + s];
                float dot = fmaf(q.z, c.z, fmaf(q.y, c.y, q.x * c.x));
                float rhs = fmaf(0.5f, c.w, qoff);
                if (dot >= rhs) {
                    float t1 = qsq + c.w;
                    float d = __fsub_rn(t1, __fmul_rn(2.0f, dot));
                    if (d <= THR && d < maxv) {
                        int j = g_sj[(b << 12) + s];
#pragma unroll
                        for (int u = 0; u < KK; u++)
                            if (u == maxslot) { bestd[u] = d; bestj[u] = j; }
                        maxv = bestd[0]; maxj = bestj[0]; maxslot = 0;
#pragma unroll
                        for (int u = 1; u < KK; u++) {
                            bool g = (bestd[u] > maxv) ||
                                     (bestd[u] == maxv && bestj[u] > maxj);
                            if (g) { maxv = bestd[u]; maxj = bestj[u]; maxslot = u; }
                        }
                    }
                }
            }
        }
    }

    const int base = (b * NN + qi) * KK;
#pragma unroll
    for (int s = 0; s < KK; s++) {
        float d = fmaxf(bestd[s], 0.0f);
        int   j = bestj[s];
        if (d > THR) { j = qi; d = 0.0f; }
        g_knn_idx[base + s]  = j;
        g_knn_dist[base + s] = d;
    }
}

// ============================================================================
// dfg kernel: W1/W2 only in SMEM (18.7KB) + 8 warps x 5.2KB hidT = 60KB
// -> 3 blocks/SM, 24 warps/SM.  One warp per point, 8 points per warp.
// Writes h67 = [agg(64) | xyz(3)] to global scratch.
// ============================================================================
#define DW    8
#define DPPW  8
#define DTPB  (DW * 32)

#define D_W1  0
#define D_B1  448
#define D_W2  512
#define D_B2  4608
#define D_SCR 4672
#define D_WS  1296
#define DSMEM_FLOATS (D_SCR + DW * D_WS)
#define DSMEM_BYTES  (DSMEM_FLOATS * 4)

__global__ __launch_bounds__(DTPB)
void dfg_kernel(const float* __restrict__ xyz,
                const float* __restrict__ points,
                const float* __restrict__ w1, const float* __restrict__ b1,
                const float* __restrict__ w2, const float* __restrict__ b2) {
    extern __shared__ float sm[];

    for (int t = threadIdx.x; t < 448; t += DTPB)  sm[D_W1 + t] = w1[t];
    for (int t = threadIdx.x; t < 64;  t += DTPB)  sm[D_B1 + t] = b1[t];
    for (int t = threadIdx.x; t < 4096; t += DTPB) sm[D_W2 + t] = w2[t];
    for (int t = threadIdx.x; t < 64;  t += DTPB)  sm[D_B2 + t] = b2[t];
    __syncthreads();

    const int warp = threadIdx.x >> 5;
    const int lane = threadIdx.x & 31;
    const int c0 = 2 * lane, c1 = c0 + 1;

    float w1r0[7], w1r1[7];
#pragma unroll
    for (int t = 0; t < 7; t++) {
        w1r0[t] = sm[D_W1 + t * 64 + c0];
        w1r1[t] = sm[D_W1 + t * 64 + c1];
    }
    const float lb10 = sm[D_B1 + c0], lb11 = sm[D_B1 + c1];
    const float lb20 = sm[D_B2 + c0], lb21 = sm[D_B2 + c1];

    float* ws = sm + D_SCR + warp * D_WS;
    const unsigned smbase = (unsigned)__cvta_generic_to_shared(sm);
    const unsigned hidT32 = smbase + (unsigned)(D_SCR + warp * D_WS) * 4u;

#pragma unroll 1
    for (int pp = 0; pp < DPPW; pp++) {
        const int p = blockIdx.x * (DW * DPPW) + warp * DPPW + pp;
        const int b = p >> 12;
        const float qx = xyz[p * 3 + 0];
        const float qy = xyz[p * 3 + 1];
        const float qz = xyz[p * 3 + 2];

        int   myidx = p & (NN - 1);
        float mydist = 0.0f;
        if (lane < KK) {
            myidx  = g_knn_idx[p * KK + lane];
            mydist = g_knn_dist[p * KK + lane];
        }

        // ---- dfg layer 1: 4 k at a time, swizzled transpose store -------
        const int sA = (c0 >> 3) & 3;
#pragma unroll
        for (int kb = 0; kb < 4; kb++) {
            float2 hk[4];
#pragma unroll
            for (int kk = 0; kk < 4; kk++) {
                const int k = kb * 4 + kk;
                const int   j  = __shfl_sync(0xffffffffu, myidx, k);
                const float dk = __shfl_sync(0xffffffffu, mydist, k);
                const float* nb = xyz + ((size_t)(b << 12) + j) * 3;
                const float g0 = nb[0], g1 = nb[1], g2 = nb[2];
                const float g3 = g0 - qx, g4 = g1 - qy, g5 = g2 - qz;
                float h0 = lb10, h1 = lb11;
                h0 = fmaf(g0, w1r0[0], h0); h1 = fmaf(g0, w1r1[0], h1);
                h0 = fmaf(g1, w1r0[1], h0); h1 = fmaf(g1, w1r1[1], h1);
                h0 = fmaf(g2, w1r0[2], h0); h1 = fmaf(g2, w1r1[2], h1);
                h0 = fmaf(g3, w1r0[3], h0); h1 = fmaf(g3, w1r1[3], h1);
                h0 = fmaf(g4, w1r0[4], h0); h1 = fmaf(g4, w1r1[4], h1);
                h0 = fmaf(g5, w1r0[5], h0); h1 = fmaf(g5, w1r1[5], h1);
                h0 = fmaf(dk, w1r0[6], h0); h1 = fmaf(dk, w1r1[6], h1);
                hk[kk] = make_float2(fmaxf(h0, 0.0f), fmaxf(h1, 0.0f));
            }
            const int slot = (kb ^ sA) << 2;
            *(float4*)(ws + c0 * 20 + slot) =
                make_float4(hk[0].x, hk[1].x, hk[2].x, hk[3].x);
            *(float4*)(ws + c1 * 20 + slot) =
                make_float4(hk[0].y, hk[1].y, hk[2].y, hk[3].y);
        }
        __syncwarp();

        // ---- dfg layer 2: 16-k batched, broadcast hid reads -------------
        u64 a0[8], a1[8];
        {
            u64 bb0 = f2pack(lb20, lb20), bb1 = f2pack(lb21, lb21);
#pragma unroll
            for (int m = 0; m < 8; m++) { a0[m] = bb0; a1[m] = bb1; }
        }
#pragma unroll
        for (int o = 0; o < 8; o++) {
#pragma unroll
            for (int tt = 0; tt < 8; tt++) {
                const int t = o * 8 + tt;
                const int sw = (t >> 3) & 3;
                const float2 w = *(const float2*)&sm[D_W2 + t * 64 + c0];
                const u64 w00 = f2pack(w.x, w.x);
                const u64 w11 = f2pack(w.y, w.y);
                const unsigned rowa = hidT32 + (unsigned)(t * 20) * 4u;
#pragma unroll
                for (int g = 0; g < 4; g++) {
                    u64 h01, h23;
                    lds2x64(h01, h23, rowa + (unsigned)(((g ^ sw) << 2) * 4));
                    const int m = g << 1;
                    a0[m]     = ffma2(h01, w00, a0[m]);
                    a0[m + 1] = ffma2(h23, w00, a0[m + 1]);
                    a1[m]     = ffma2(h01, w11, a1[m]);
                    a1[m + 1] = ffma2(h23, w11, a1[m + 1]);
                }
            }
        }
        __syncwarp();

        // ---- aggregation over k -----------------------------------------
        float agg0 = 0.0f, agg1 = 0.0f;
#pragma unroll
        for (int m = 0; m < 8; m++) {
            float oE0, oO0, oE1, oO1;
            f2unpack(a0[m], oE0, oO0);
            f2unpack(a1[m], oE1, oO1);
#pragma unroll
            for (int kk = 0; kk < 2; kk++) {
                const int k = 2 * m + kk;
                const float o0 = kk ? oO0 : oE0;
                const float o1 = kk ? oO1 : oE1;
                const int   j  = __shfl_sync(0xffffffffu, myidx, k);
                const float dk = __shfl_sync(0xffffffffu, mydist, k);
                const float* nb = xyz + ((size_t)(b << 12) + j) * 3;
                const float g0 = nb[0], g1 = nb[1], g2 = nb[2];
                const float* prow = points + ((size_t)(b << 12) + j) * CPN;
                float gp0 = (c0 >= 7) ? prow[c0 - 7] : 0.0f;
                float gp1 = (c1 >= 7) ? prow[c1 - 7] : 0.0f;
                if (lane == 0)      { gp0 = g0; gp1 = g1; }
                else if (lane == 1) { gp0 = g2; gp1 = g0 - qx; }
                else if (lane == 2) { gp0 = g1 - qy; gp1 = g2 - qz; }
                else if (lane == 3) { gp0 = dk; }
                agg0 = fmaf(o0, gp0, agg0);
                agg1 = fmaf(o1, gp1, agg1);
            }
        }
        agg0 *= 0.0625f; agg1 *= 0.0625f;

        float* hb = g_h67 + (size_t)p * 68;
        *(float2*)&hb[c0] = make_float2(agg0, agg1);
        if (lane == 0) { hb[64] = qx; hb[65] = qy; hb[66] = qz; }
        __syncwarp();
    }
}

// ============================================================================
// mlp kernel: M1/M2/SC in SMEM (82.7KB) + 8 warps x 3.2KB = 108KB
// -> 2 blocks/SM.  4 points per warp share every weight row.
// ============================================================================
#define MW    8
#define MPPW  4
#define MTPB  (MW * 32)

#define M_M1   0
#define M_MB1  8576
#define M_M2   8704
#define M_MB2  16896
#define M_SC   16960
#define M_SCB  20608
#define M_SCR  20672
#define M_WS   800              // h67b (4x68=272) + h128b (4x128=512) + pad
#define MSMEM_FLOATS (M_SCR + MW * M_WS)
#define MSMEM_BYTES  (MSMEM_FLOATS * 4)

__global__ __launch_bounds__(MTPB)
void mlp_kernel(const float* __restrict__ points,
                const float* __restrict__ m1, const float* __restrict__ mb1,
                const float* __restrict__ m2, const float* __restrict__ mb2,
                const float* __restrict__ sc, const float* __restrict__ scb,
                float* __restrict__ out) {
    extern __shared__ float sm[];

    for (int t = threadIdx.x; t < 8576; t += MTPB) sm[M_M1 + t]  = m1[t];
    for (int t = threadIdx.x; t < 128; t += MTPB)  sm[M_MB1 + t] = mb1[t];
    for (int t = threadIdx.x; t < 8192; t += MTPB) sm[M_M2 + t]  = m2[t];
    for (int t = threadIdx.x; t < 64;  t += MTPB)  sm[M_MB2 + t] = mb2[t];
    for (int t = threadIdx.x; t < 3648; t += MTPB) sm[M_SC + t]  = sc[t];
    for (int t = threadIdx.x; t < 64;  t += MTPB)  sm[M_SCB + t] = scb[t];
    __syncthreads();

    const int warp = threadIdx.x >> 5;
    const int lane = threadIdx.x & 31;
    const int c0 = 2 * lane, c1 = c0 + 1;
    const int c4 = 4 * lane;

    float* h67b  = sm + M_SCR + warp * M_WS;   // 4 x 68, later reused as prow
    float* h128b = h67b + 272;                  // 4 x 128

    const unsigned smbase = (unsigned)__cvta_generic_to_shared(sm);
    const int pbase = blockIdx.x * (MW * MPPW) + warp * MPPW;

    // stage h67 rows
#pragma unroll
    for (int pp = 0; pp < MPPW; pp++) {
        const float* src = g_h67 + (size_t)(pbase + pp) * 68;
        for (int t = lane; t < 68; t += 32) h67b[pp * 68 + t] = src[t];
    }
    __syncwarp();

    // mlp1: [67] -> [128], relu.  input order = [xyz(3), agg(64)]
    {
        u64 acc[MPPW][2];
        const float4 bbv = *(const float4*)&sm[M_MB1 + c4];
        const u64 bb01 = f2pack(bbv.x, bbv.y), bb23 = f2pack(bbv.z, bbv.w);
#pragma unroll
        for (int pp = 0; pp < MPPW; pp++) { acc[pp][0] = bb01; acc[pp][1] = bb23; }
        const unsigned m1base = smbase + (unsigned)(M_M1 + c4) * 4u;

#pragma unroll
        for (int t = 0; t < 3; t++) {          // xyz rows
            u64 w01, w23; lds2x64(w01, w23, m1base + (unsigned)(t * 128) * 4u);
#pragma unroll
            for (int pp = 0; pp < MPPW; pp++) {
                const float v = h67b[pp * 68 + 64 + t];
                const u64 vv = f2pack(v, v);
                acc[pp][0] = ffma2(w01, vv, acc[pp][0]);
                acc[pp][1] = ffma2(w23, vv, acc[pp][1]);
            }
        }
#pragma unroll 4
        for (int i = 0; i < 64; i++) {         // agg rows
            u64 w01, w23; lds2x64(w01, w23, m1base + (unsigned)((3 + i) * 128) * 4u);
#pragma unroll
            for (int pp = 0; pp < MPPW; pp++) {
                const float v = h67b[pp * 68 + i];
                const u64 vv = f2pack(v, v);
                acc[pp][0] = ffma2(w01, vv, acc[pp][0]);
                acc[pp][1] = ffma2(w23, vv, acc[pp][1]);
            }
        }
        __syncwarp();
#pragma unroll
        for (int pp = 0; pp < MPPW; pp++) {
            float x0, x1, x2, x3;
            f2unpack(acc[pp][0], x0, x1);
            f2unpack(acc[pp][1], x2, x3);
            *(float4*)&h128b[pp * 128 + c4] =
                make_float4(fmaxf(x0, 0.0f), fmaxf(x1, 0.0f),
                            fmaxf(x2, 0.0f), fmaxf(x3, 0.0f));
        }
    }
    __syncwarp();

    // reuse h67b as prow staging (mlp1 reads complete)
#pragma unroll
    for (int pp = 0; pp < MPPW; pp++) {
        const float* ps = points + (size_t)(pbase + pp) * CPN;
        for (int t = lane; t < CPN; t += 32) h67b[pp * 68 + t] = ps[t];
    }
    __syncwarp();

    // mlp2: [128] -> [64]
    u64 om[MPPW];
    {
        const u64 mb = *(const u64*)&sm[M_MB2 + c0];
#pragma unroll
        for (int pp = 0; pp < MPPW; pp++) om[pp] = mb;
#pragma unroll 4
        for (int t = 0; t < 128; t++) {
            const u64 wp = *(const u64*)&sm[M_M2 + t * 64 + c0];
#pragma unroll
            for (int pp = 0; pp < MPPW; pp++) {
                const float v = h128b[pp * 128 + t];
                om[pp] = ffma2(wp, f2pack(v, v), om[pp]);
            }
        }
    }

    // shortcut: points @ sc_w + sc_b
    u64 orr[MPPW];
    {
        const u64 sb = *(const u64*)&sm[M_SCB + c0];
#pragma unroll
        for (int pp = 0; pp < MPPW; pp++) orr[pp] = sb;
#pragma unroll 4
        for (int t = 0; t < CPN; t++) {
            const u64 wp = *(const u64*)&sm[M_SC + t * 64 + c0];
#pragma unroll
            for (int pp = 0; pp < MPPW; pp++) {
                const float v = h67b[pp * 68 + t];
                orr[pp] = ffma2(wp, f2pack(v, v), orr[pp]);
            }
        }
    }

#pragma unroll
    for (int pp = 0; pp < MPPW; pp++) {
        float o0, o1, r0, r1;
        f2unpack(om[pp], o0, o1);
        f2unpack(orr[pp], r0, r1);
        const int p = pbase + pp;
        *(float2*)&out[(size_t)p * 64 + c0] =
            make_float2(fmaxf(r0 + o0, 0.0f), fmaxf(r1 + o1, 0.0f));
    }
}

// ============================================================================
extern "C" void kernel_launch(void* const* d_in, const int* in_sizes, int n_in,
                              void* d_out, int out_size) {
    const float* xyz    = (const float*)d_in[0];
    const float* points = (const float*)d_in[1];
    const float* w1     = (const float*)d_in[2];
    const float* b1     = (const float*)d_in[3];
    const float* w2     = (const float*)d_in[4];
    const float* b2     = (const float*)d_in[5];
    const float* m1     = (const float*)d_in[6];
    const float* mb1    = (const float*)d_in[7];
    const float* m2     = (const float*)d_in[8];
    const float* mb2    = (const float*)d_in[9];
    const float* sc     = (const float*)d_in[10];
    const float* scb    = (const float*)d_in[11];
    float* out = (float*)d_out;
    (void)in_sizes; (void)n_in; (void)out_size;

    grid_build<<<BB, 512>>>(xyz);
    knn_query<<<dim3(NN / 128, BB), 128>>>();

    cudaFuncSetAttribute(dfg_kernel,
                         cudaFuncAttributeMaxDynamicSharedMemorySize,
                         DSMEM_BYTES);
    dfg_kernel<<<BB * NN / (DW * DPPW), DTPB, DSMEM_BYTES>>>(
        xyz, points, w1, b1, w2, b2);

    cudaFuncSetAttribute(mlp_kernel,
                         cudaFuncAttributeMaxDynamicSharedMemorySize,
                         MSMEM_BYTES);
    mlp_kernel<<<BB * NN / (MW * MPPW), MTPB, MSMEM_BYTES>>>(
        points, m1, mb1, m2, mb2, sc, scb, out);
}

// round 6
// speedup vs baseline: 1.2289x; 1.0142x over previous
#include <cuda_runtime.h>
#include <stdint.h>

#define BB   8
#define NN   4096
#define CPN  57
#define KK   16
#define THR  0.04f
#define NC   125
#define NBIN 64
#define TCAP 20

// ---------------- scratch (device globals; no allocation allowed) -----------
__device__ int2   g_knn_pair[BB * NN * KK];   // (idx, dist bits) interleaved
__device__ int    g_off[BB * 128];
__device__ float4 g_sx[BB * NN];
__device__ int    g_sj[BB * NN];
__device__ float  g_h67[BB * NN * 68];        // [agg(64) | xyz(3) | pad]

// ---------------------------------------------------------------------------
// f32x2 packed helpers
// ---------------------------------------------------------------------------
typedef unsigned long long u64;
__device__ __forceinline__ u64 f2pack(float a, float b) {
    u64 r; asm("mov.b64 %0,{%1,%2};" : "=l"(r) : "f"(a), "f"(b)); return r;
}
__device__ __forceinline__ void f2unpack(u64 v, float& a, float& b) {
    asm("mov.b64 {%0,%1},%2;" : "=f"(a), "=f"(b) : "l"(v));
}
__device__ __forceinline__ u64 ffma2(u64 a, u64 b, u64 c) {
    u64 d; asm("fma.rn.f32x2 %0,%1,%2,%3;" : "=l"(d) : "l"(a), "l"(b), "l"(c));
    return d;
}
__device__ __forceinline__ void lds2x64(u64& a, u64& b, unsigned addr) {
    asm volatile("ld.shared.v2.b64 {%0,%1},[%2];"
                 : "=l"(a), "=l"(b) : "r"(addr));
}

// ---------------------------------------------------------------------------
// Fused grid build: one block per batch.  count -> scan -> scatter in SMEM.
// ---------------------------------------------------------------------------
__device__ __forceinline__ int cell_of(float x, float y, float z) {
    int cx = min((int)(x * 5.0f), 4);
    int cy = min((int)(y * 5.0f), 4);
    int cz = min((int)(z * 5.0f), 4);
    return (cx * 5 + cy) * 5 + cz;
}

__global__ void grid_build(const float* __restrict__ xyz) {
    __shared__ int scnt[NC];
    __shared__ int soff[NC + 1];
    __shared__ int scur[NC];
    const int b = blockIdx.x;
    const float* bx = xyz + (size_t)b * NN * 3;

    for (int t = threadIdx.x; t < NC; t += 512) scnt[t] = 0;
    __syncthreads();

    for (int i = threadIdx.x; i < NN; i += 512) {
        float x = bx[i * 3 + 0], y = bx[i * 3 + 1], z = bx[i * 3 + 2];
        atomicAdd(&scnt[cell_of(x, y, z)], 1);
    }
    __syncthreads();

    if (threadIdx.x == 0) {
        int acc = 0;
        for (int c = 0; c < NC; c++) { soff[c] = acc; scur[c] = acc; acc += scnt[c]; }
        soff[NC] = acc;
    }
    __syncthreads();

    for (int t = threadIdx.x; t <= NC; t += 512) g_off[b * 128 + t] = soff[t];

    for (int i = threadIdx.x; i < NN; i += 512) {
        float x = bx[i * 3 + 0], y = bx[i * 3 + 1], z = bx[i * 3 + 2];
        int cell = cell_of(x, y, z);
        int pos = atomicAdd(&scur[cell], 1);
        float sq = fmaf(z, z, fmaf(y, y, x * x));
        g_sx[(b << 12) + pos] = make_float4(x, y, z, sq);
        g_sj[(b << 12) + pos] = i;
    }
}

// ---------------------------------------------------------------------------
// kNN query: histogram two-pass selection (no divergent top-K inserts).
// Pass A bins exact d; prefix locates threshold bin t*; pass B streams
// bins < t* directly to global and resolves bin == t* by exact (d, j) order.
// Both passes evaluate identical expressions -> identical d bits.
// SMEM: hist 16KB (ushort) + tl 20KB = 36.9KB < 48KB static limit.
// ---------------------------------------------------------------------------
#define KNN_SCAN(BODY)                                                        \
    for (int dx = -1; dx <= 1; dx++) {                                        \
        int ncx = cx + dx; if (ncx < 0 || ncx > 4) continue;                  \
        for (int dy = -1; dy <= 1; dy++) {                                    \
            int ncy = cy + dy; if (ncy < 0 || ncy > 4) continue;              \
            int cb2 = b * 128 + (ncx * 5 + ncy) * 5;                          \
            int sbeg = g_off[cb2 + czlo];                                     \
            int send = g_off[cb2 + czhi + 1];                                 \
            for (int s = sbeg; s < send; s++) {                               \
                float4 c = g_sx[(b << 12) + s];                               \
                float dot = fmaf(q.z, c.z, fmaf(q.y, c.y, q.x * c.x));        \
                float rhs = fmaf(0.5f, c.w, qoff);                            \
                if (dot >= rhs) {                                             \
                    float t1 = qsq + c.w;                                     \
                    float d = __fsub_rn(t1, __fmul_rn(2.0f, dot));            \
                    if (d <= THR) { BODY }                                    \
                }                                                             \
            }                                                                 \
        }                                                                     \
    }

__global__ __launch_bounds__(128) void knn_query() {
    __shared__ unsigned short hist[NBIN * 128];
    __shared__ int2 tl[128 * TCAP];
    const int tid = threadIdx.x;
    const int b = blockIdx.y;
    const int slot = blockIdx.x * 128 + tid;
    const float4 q = g_sx[(b << 12) + slot];
    const int qi = g_sj[(b << 12) + slot];
    const float qsq = q.w;
    const int cx = min((int)(q.x * 5.0f), 4);
    const int cy = min((int)(q.y * 5.0f), 4);
    const int cz = min((int)(q.z * 5.0f), 4);
    const float qoff = 0.5f * (qsq - THR) - 1e-5f;
    const int czlo = max(cz - 1, 0), czhi = min(cz + 1, 4);

#pragma unroll 8
    for (int bn = 0; bn < NBIN; bn++) hist[bn * 128 + tid] = 0;

    // ---- pass A: histogram of exact d -----------------------------------
    KNN_SCAN({
        int bn = max(0, min(NBIN - 1, (int)(d * 1600.0f)));   // 64 / 0.04
        hist[bn * 128 + tid]++;
    })

    // ---- threshold: smallest bin with cum >= K --------------------------
    int tstar = NBIN, cum = 0;
#pragma unroll 8
    for (int bn = 0; bn < NBIN; bn++) {
        int c = (int)hist[bn * 128 + tid];
        if (tstar == NBIN && cum + c >= KK) tstar = bn;
        cum += c;
    }

    const int base = (b * NN + qi) * KK;
    int cnt = 0, tcnt = 0;

    // ---- pass B: direct-stream + threshold list -------------------------
    KNN_SCAN({
        int bn = max(0, min(NBIN - 1, (int)(d * 1600.0f)));
        if (bn < tstar) {
            int j = g_sj[(b << 12) + s];
            g_knn_pair[base + cnt] =
                make_int2(j, __float_as_int(fmaxf(d, 0.0f)));
            cnt++;
        } else if (bn == tstar && tcnt < TCAP) {
            int j = g_sj[(b << 12) + s];
            tl[tid * TCAP + tcnt] = make_int2(j, __float_as_int(d));
            tcnt++;
        }
    })

    // ---- resolve threshold bin by exact (d, j) lexicographic order ------
    if (tstar < NBIN) {
        int need = KK - cnt;
        if (need > tcnt) need = tcnt;
        for (int s2 = 0; s2 < need; s2++) {
            float bd = 3.0e38f; int bj = 0x7fffffff, bi = -1;
            for (int i2 = 0; i2 < tcnt; i2++) {
                int2 e = tl[tid * TCAP + i2];
                float dv = __int_as_float(e.y);
                bool g = (dv < bd) || (dv == bd && e.x < bj);
                if (g) { bd = dv; bj = e.x; bi = i2; }
            }
            tl[tid * TCAP + bi].y = __float_as_int(3.0e38f);
            g_knn_pair[base + cnt] =
                make_int2(bj, __float_as_int(fmaxf(bd, 0.0f)));
            cnt++;
        }
    }
    for (; cnt < KK; cnt++) g_knn_pair[base + cnt] = make_int2(qi, 0);
}

// ============================================================================
// dfg kernel: W1/W2 in SMEM (18.7KB) + 8 warps x 5.2KB hidT = 60KB
// -> 3 blocks/SM.  knn pairs read via uniform broadcast LDG.64 (no shfl).
// ============================================================================
#define DW    8
#define DPPW  8
#define DTPB  (DW * 32)

#define D_W1  0
#define D_B1  448
#define D_W2  512
#define D_B2  4608
#define D_SCR 4672
#define D_WS  1296
#define DSMEM_FLOATS (D_SCR + DW * D_WS)
#define DSMEM_BYTES  (DSMEM_FLOATS * 4)

__global__ __launch_bounds__(DTPB)
void dfg_kernel(const float* __restrict__ xyz,
                const float* __restrict__ points,
                const float* __restrict__ w1, const float* __restrict__ b1,
                const float* __restrict__ w2, const float* __restrict__ b2) {
    extern __shared__ float sm[];

    for (int t = threadIdx.x; t < 448; t += DTPB)  sm[D_W1 + t] = w1[t];
    for (int t = threadIdx.x; t < 64;  t += DTPB)  sm[D_B1 + t] = b1[t];
    for (int t = threadIdx.x; t < 4096; t += DTPB) sm[D_W2 + t] = w2[t];
    for (int t = threadIdx.x; t < 64;  t += DTPB)  sm[D_B2 + t] = b2[t];
    __syncthreads();

    const int warp = threadIdx.x >> 5;
    const int lane = threadIdx.x & 31;
    const int c0 = 2 * lane, c1 = c0 + 1;

    float w1r0[7], w1r1[7];
#pragma unroll
    for (int t = 0; t < 7; t++) {
        w1r0[t] = sm[D_W1 + t * 64 + c0];
        w1r1[t] = sm[D_W1 + t * 64 + c1];
    }
    const float lb10 = sm[D_B1 + c0], lb11 = sm[D_B1 + c1];
    const float lb20 = sm[D_B2 + c0], lb21 = sm[D_B2 + c1];

    float* ws = sm + D_SCR + warp * D_WS;
    const unsigned hidT32 =
        (unsigned)__cvta_generic_to_shared(sm) +
        (unsigned)(D_SCR + warp * D_WS) * 4u;

#pragma unroll 1
    for (int pp = 0; pp < DPPW; pp++) {
        const int p = blockIdx.x * (DW * DPPW) + warp * DPPW + pp;
        const int b = p >> 12;
        const float qx = xyz[p * 3 + 0];
        const float qy = xyz[p * 3 + 1];
        const float qz = xyz[p * 3 + 2];
        const int2* kp = g_knn_pair + (size_t)p * KK;

        // ---- dfg layer 1: 4 k at a time, swizzled transpose store -------
        const int sA = (c0 >> 3) & 3;
#pragma unroll
        for (int kb = 0; kb < 4; kb++) {
            float2 hk[4];
#pragma unroll
            for (int kk = 0; kk < 4; kk++) {
                const int2 pr = kp[kb * 4 + kk];     // uniform broadcast LDG
                const int   j  = pr.x;
                const float dk = __int_as_float(pr.y);
                const float* nb = xyz + ((size_t)(b << 12) + j) * 3;
                const float g0 = nb[0], g1 = nb[1], g2 = nb[2];
                const float g3 = g0 - qx, g4 = g1 - qy, g5 = g2 - qz;
                float h0 = lb10, h1 = lb11;
                h0 = fmaf(g0, w1r0[0], h0); h1 = fmaf(g0, w1r1[0], h1);
                h0 = fmaf(g1, w1r0[1], h0); h1 = fmaf(g1, w1r1[1], h1);
                h0 = fmaf(g2, w1r0[2], h0); h1 = fmaf(g2, w1r1[2], h1);
                h0 = fmaf(g3, w1r0[3], h0); h1 = fmaf(g3, w1r1[3], h1);
                h0 = fmaf(g4, w1r0[4], h0); h1 = fmaf(g4, w1r1[4], h1);
                h0 = fmaf(g5, w1r0[5], h0); h1 = fmaf(g5, w1r1[5], h1);
                h0 = fmaf(dk, w1r0[6], h0); h1 = fmaf(dk, w1r1[6], h1);
                hk[kk] = make_float2(fmaxf(h0, 0.0f), fmaxf(h1, 0.0f));
            }
            const int slot = (kb ^ sA) << 2;
            *(float4*)(ws + c0 * 20 + slot) =
                make_float4(hk[0].x, hk[1].x, hk[2].x, hk[3].x);
            *(float4*)(ws + c1 * 20 + slot) =
                make_float4(hk[0].y, hk[1].y, hk[2].y, hk[3].y);
        }
        __syncwarp();

        // ---- dfg layer 2: 16-k batched, broadcast hid reads -------------
        u64 a0[8], a1[8];
        {
            u64 bb0 = f2pack(lb20, lb20), bb1 = f2pack(lb21, lb21);
#pragma unroll
            for (int m = 0; m < 8; m++) { a0[m] = bb0; a1[m] = bb1; }
        }
#pragma unroll
        for (int o = 0; o < 8; o++) {
#pragma unroll
            for (int tt = 0; tt < 8; tt++) {
                const int t = o * 8 + tt;
                const int sw = (t >> 3) & 3;
                const float2 w = *(const float2*)&sm[D_W2 + t * 64 + c0];
                const u64 w00 = f2pack(w.x, w.x);
                const u64 w11 = f2pack(w.y, w.y);
                const unsigned rowa = hidT32 + (unsigned)(t * 20) * 4u;
#pragma unroll
                for (int g = 0; g < 4; g++) {
                    u64 h01, h23;
                    lds2x64(h01, h23, rowa + (unsigned)(((g ^ sw) << 2) * 4));
                    const int m = g << 1;
                    a0[m]     = ffma2(h01, w00, a0[m]);
                    a0[m + 1] = ffma2(h23, w00, a0[m + 1]);
                    a1[m]     = ffma2(h01, w11, a1[m]);
                    a1[m + 1] = ffma2(h23, w11, a1[m + 1]);
                }
            }
        }
        __syncwarp();

        // ---- aggregation over k -----------------------------------------
        float agg0 = 0.0f, agg1 = 0.0f;
#pragma unroll
        for (int m = 0; m < 8; m++) {
            float oE0, oO0, oE1, oO1;
            f2unpack(a0[m], oE0, oO0);
            f2unpack(a1[m], oE1, oO1);
#pragma unroll
            for (int kk = 0; kk < 2; kk++) {
                const int k = 2 * m + kk;
                const float o0 = kk ? oO0 : oE0;
                const float o1 = kk ? oO1 : oE1;
                const int2 pr = kp[k];               // L1-hit broadcast
                const int   j  = pr.x;
                const float dk = __int_as_float(pr.y);
                const float* nb = xyz + ((size_t)(b << 12) + j) * 3;
                const float g0 = nb[0], g1 = nb[1], g2 = nb[2];
                const float* prow = points + ((size_t)(b << 12) + j) * CPN;
                float gp0 = (c0 >= 7) ? prow[c0 - 7] : 0.0f;
                float gp1 = (c1 >= 7) ? prow[c1 - 7] : 0.0f;
                if (lane == 0)      { gp0 = g0; gp1 = g1; }
                else if (lane == 1) { gp0 = g2; gp1 = g0 - qx; }
                else if (lane == 2) { gp0 = g1 - qy; gp1 = g2 - qz; }
                else if (lane == 3) { gp0 = dk; }
                agg0 = fmaf(o0, gp0, agg0);
                agg1 = fmaf(o1, gp1, agg1);
            }
        }
        agg0 *= 0.0625f; agg1 *= 0.0625f;

        float* hb = g_h67 + (size_t)p * 68;
        *(float2*)&hb[c0] = make_float2(agg0, agg1);
        if (lane == 0) { hb[64] = qx; hb[65] = qy; hb[66] = qz; }
        __syncwarp();
    }
}

// ============================================================================
// mlp kernel: M1/M2/SC in SMEM (82.7KB) + 8 warps x 3.2KB = 108KB
// -> 2 blocks/SM.  4 points per warp share every weight row.
// ============================================================================
#define MW    8
#define MPPW  4
#define MTPB  (MW * 32)

#define M_M1   0
#define M_MB1  8576
#define M_M2   8704
#define M_MB2  16896
#define M_SC   16960
#define M_SCB  20608
#define M_SCR  20672
#define M_WS   800
#define MSMEM_FLOATS (M_SCR + MW * M_WS)
#define MSMEM_BYTES  (MSMEM_FLOATS * 4)

__global__ __launch_bounds__(MTPB)
void mlp_kernel(const float* __restrict__ points,
                const float* __restrict__ m1, const float* __restrict__ mb1,
                const float* __restrict__ m2, const float* __restrict__ mb2,
                const float* __restrict__ sc, const float* __restrict__ scb,
                float* __restrict__ out) {
    extern __shared__ float sm[];

    for (int t = threadIdx.x; t < 8576; t += MTPB) sm[M_M1 + t]  = m1[t];
    for (int t = threadIdx.x; t < 128; t += MTPB)  sm[M_MB1 + t] = mb1[t];
    for (int t = threadIdx.x; t < 8192; t += MTPB) sm[M_M2 + t]  = m2[t];
    for (int t = threadIdx.x; t < 64;  t += MTPB)  sm[M_MB2 + t] = mb2[t];
    for (int t = threadIdx.x; t < 3648; t += MTPB) sm[M_SC + t]  = sc[t];
    for (int t = threadIdx.x; t < 64;  t += MTPB)  sm[M_SCB + t] = scb[t];
    __syncthreads();

    const int warp = threadIdx.x >> 5;
    const int lane = threadIdx.x & 31;
    const int c0 = 2 * lane;
    const int c4 = 4 * lane;

    float* h67b  = sm + M_SCR + warp * M_WS;
    float* h128b = h67b + 272;

    const unsigned smbase = (unsigned)__cvta_generic_to_shared(sm);
    const int pbase = blockIdx.x * (MW * MPPW) + warp * MPPW;

#pragma unroll
    for (int pp = 0; pp < MPPW; pp++) {
        const float* src = g_h67 + (size_t)(pbase + pp) * 68;
        for (int t = lane; t < 68; t += 32) h67b[pp * 68 + t] = src[t];
    }
    __syncwarp();

    // mlp1: [67] -> [128], relu.  input order = [xyz(3), agg(64)]
    {
        u64 acc[MPPW][2];
        const float4 bbv = *(const float4*)&sm[M_MB1 + c4];
        const u64 bb01 = f2pack(bbv.x, bbv.y), bb23 = f2pack(bbv.z, bbv.w);
#pragma unroll
        for (int pp = 0; pp < MPPW; pp++) { acc[pp][0] = bb01; acc[pp][1] = bb23; }
        const unsigned m1base = smbase + (unsigned)(M_M1 + c4) * 4u;

#pragma unroll
        for (int t = 0; t < 3; t++) {
            u64 w01, w23; lds2x64(w01, w23, m1base + (unsigned)(t * 128) * 4u);
#pragma unroll
            for (int pp = 0; pp < MPPW; pp++) {
                const float v = h67b[pp * 68 + 64 + t];
                const u64 vv = f2pack(v, v);
                acc[pp][0] = ffma2(w01, vv, acc[pp][0]);
                acc[pp][1] = ffma2(w23, vv, acc[pp][1]);
            }
        }
#pragma unroll 4
        for (int i = 0; i < 64; i++) {
            u64 w01, w23; lds2x64(w01, w23, m1base + (unsigned)((3 + i) * 128) * 4u);
#pragma unroll
            for (int pp = 0; pp < MPPW; pp++) {
                const float v = h67b[pp * 68 + i];
                const u64 vv = f2pack(v, v);
                acc[pp][0] = ffma2(w01, vv, acc[pp][0]);
                acc[pp][1] = ffma2(w23, vv, acc[pp][1]);
            }
        }
        __syncwarp();
#pragma unroll
        for (int pp = 0; pp < MPPW; pp++) {
            float x0, x1, x2, x3;
            f2unpack(acc[pp][0], x0, x1);
            f2unpack(acc[pp][1], x2, x3);
            *(float4*)&h128b[pp * 128 + c4] =
                make_float4(fmaxf(x0, 0.0f), fmaxf(x1, 0.0f),
                            fmaxf(x2, 0.0f), fmaxf(x3, 0.0f));
        }
    }
    __syncwarp();

#pragma unroll
    for (int pp = 0; pp < MPPW; pp++) {
        const float* ps = points + (size_t)(pbase + pp) * CPN;
        for (int t = lane; t < CPN; t += 32) h67b[pp * 68 + t] = ps[t];
    }
    __syncwarp();

    // mlp2: [128] -> [64]
    u64 om[MPPW];
    {
        const u64 mb = *(const u64*)&sm[M_MB2 + c0];
#pragma unroll
        for (int pp = 0; pp < MPPW; pp++) om[pp] = mb;
#pragma unroll 4
        for (int t = 0; t < 128; t++) {
            const u64 wp = *(const u64*)&sm[M_M2 + t * 64 + c0];
#pragma unroll
            for (int pp = 0; pp < MPPW; pp++) {
                const float v = h128b[pp * 128 + t];
                om[pp] = ffma2(wp, f2pack(v, v), om[pp]);
            }
        }
    }

    // shortcut: points @ sc_w + sc_b
    u64 orr[MPPW];
    {
        const u64 sb = *(const u64*)&sm[M_SCB + c0];
#pragma unroll
        for (int pp = 0; pp < MPPW; pp++) orr[pp] = sb;
#pragma unroll 4
        for (int t = 0; t < CPN; t++) {
            const u64 wp = *(const u64*)&sm[M_SC + t * 64 + c0];
#pragma unroll
            for (int pp = 0; pp < MPPW; pp++) {
                const float v = h67b[pp * 68 + t];
                orr[pp] = ffma2(wp, f2pack(v, v), orr[pp]);
            }
        }
    }

#pragma unroll
    for (int pp = 0; pp < MPPW; pp++) {
        float o0, o1, r0, r1;
        f2unpack(om[pp], o0, o1);
        f2unpack(orr[pp], r0, r1);
        const int p = pbase + pp;
        *(float2*)&out[(size_t)p * 64 + c0] =
            make_float2(fmaxf(r0 + o0, 0.0f), fmaxf(r1 + o1, 0.0f));
    }
}

// ============================================================================
extern "C" void kernel_launch(void* const* d_in, const int* in_sizes, int n_in,
                              void* d_out, int out_size) {
    const float* xyz    = (const float*)d_in[0];
    const float* points = (const float*)d_in[1];
    const float* w1     = (const float*)d_in[2];
    const float* b1     = (const float*)d_in[3];
    const float* w2     = (const float*)d_in[4];
    const float* b2     = (const float*)d_in[5];
    const float* m1     = (const float*)d_in[6];
    const float* mb1    = (const float*)d_in[7];
    const float* m2     = (const float*)d_in[8];
    const float* mb2    = (const float*)d_in[9];
    const float* sc     = (const float*)d_in[10];
    const float* scb    = (const float*)d_in[11];
    float* out = (float*)d_out;
    (void)in_sizes; (void)n_in; (void)out_size;

    grid_build<<<BB, 512>>>(xyz);
    knn_query<<<dim3(NN / 128, BB), 128>>>();

    cudaFuncSetAttribute(dfg_kernel,
                         cudaFuncAttributeMaxDynamicSharedMemorySize,
                         DSMEM_BYTES);
    dfg_kernel<<<BB * NN / (DW * DPPW), DTPB, DSMEM_BYTES>>>(
        xyz, points, w1, b1, w2, b2);

    cudaFuncSetAttribute(mlp_kernel,
                         cudaFuncAttributeMaxDynamicSharedMemorySize,
                         MSMEM_BYTES);
    mlp_kernel<<<BB * NN / (MW * MPPW), MTPB, MSMEM_BYTES>>>(
        points, m1, mb1, m2, mb2, sc, scb, out);
}